// round 1
// baseline (speedup 1.0000x reference)
#include <cuda_runtime.h>

#define D      1024
#define NTOK   2048
#define NB     4
#define MTOT   8192   // NB * NTOK
#define NSPLIT 4

// ---- scratch (device globals: allocation-free rule) ----
__device__ float g_q[MTOT * D];          // 32 MB
__device__ float g_k[MTOT * D];          // 32 MB
__device__ float g_s[MTOT];              // s[b,m] = v[b,m,:]·Ww
__device__ float g_u[D];                 // u = Ww @ Wv
__device__ float g_c;                    // c = Ww · bv
__device__ float g_part[MTOT * NSPLIT * 3]; // per-split (max, num, den)

// ---------------------------------------------------------------------------
// Kernel 1: u[e] = sum_d Ww[d] * Wv[d][e];  c = sum_d Ww[d]*bv[d]
// ---------------------------------------------------------------------------
__global__ void prep_u_kernel(const float* __restrict__ Wv,
                              const float* __restrict__ bv,
                              const float* __restrict__ Ww) {
    if (blockIdx.x < 4) {
        int e = blockIdx.x * 256 + threadIdx.x;
        float sum = 0.f;
        #pragma unroll 8
        for (int d = 0; d < D; d++) sum = fmaf(Ww[d], Wv[d * D + e], sum);
        g_u[e] = sum;
    } else {
        __shared__ float red[256];
        float s = 0.f;
        for (int d = threadIdx.x; d < D; d += 256) s = fmaf(Ww[d], bv[d], s);
        red[threadIdx.x] = s;
        __syncthreads();
        for (int off = 128; off > 0; off >>= 1) {
            if (threadIdx.x < off) red[threadIdx.x] += red[threadIdx.x + off];
            __syncthreads();
        }
        if (threadIdx.x == 0) g_c = red[0];
    }
}

// ---------------------------------------------------------------------------
// Kernel 2: s[row] = x[row,:]·u + c    (one warp per row)
// ---------------------------------------------------------------------------
__global__ void s_kernel(const float* __restrict__ x) {
    int row  = blockIdx.x * 8 + (threadIdx.x >> 5);
    int lane = threadIdx.x & 31;
    const float4* xr = (const float4*)(x + (long)row * D);
    const float4* u4 = (const float4*)g_u;
    float sum = 0.f;
    #pragma unroll
    for (int i = 0; i < 8; i++) {
        float4 a = xr[lane + i * 32];
        float4 b = u4[lane + i * 32];
        sum += a.x * b.x + a.y * b.y + a.z * b.z + a.w * b.w;
    }
    #pragma unroll
    for (int off = 16; off > 0; off >>= 1)
        sum += __shfl_xor_sync(0xffffffffu, sum, off);
    if (lane == 0) g_s[row] = sum + g_c;
}

// ---------------------------------------------------------------------------
// Kernel 3: q = x@Wq^T + bq ; k = x@Wk^T + bk   (blockIdx.z selects q/k)
// 128x128 tile, K-step 16, 256 threads, 8x8 per thread
// ---------------------------------------------------------------------------
__global__ __launch_bounds__(256)
void qk_gemm_kernel(const float* __restrict__ x,
                    const float* __restrict__ Wq, const float* __restrict__ bq,
                    const float* __restrict__ Wk, const float* __restrict__ bk) {
    const float* Wm   = blockIdx.z ? Wk : Wq;
    const float* bias = blockIdx.z ? bk : bq;
    float* out        = blockIdx.z ? g_k : g_q;
    const int row0 = blockIdx.x * 128;
    const int col0 = blockIdx.y * 128;

    __shared__ float As[16][132];
    __shared__ float Bs[16][132];

    const int tid = threadIdx.x;
    const int tx = tid & 15, ty = tid >> 4;
    const int lr = tid >> 2;          // load row (0..63), +64 for second slot
    const int lk = (tid & 3) << 2;    // k offset 0,4,8,12

    float acc[8][8];
    #pragma unroll
    for (int i = 0; i < 8; i++)
        #pragma unroll
        for (int j = 0; j < 8; j++) acc[i][j] = 0.f;

    for (int kk = 0; kk < D; kk += 16) {
        #pragma unroll
        for (int s = 0; s < 2; s++) {
            int r = lr + s * 64;
            float4 va = *(const float4*)&x [(long)(row0 + r) * D + kk + lk];
            As[lk + 0][r] = va.x; As[lk + 1][r] = va.y;
            As[lk + 2][r] = va.z; As[lk + 3][r] = va.w;
            float4 vb = *(const float4*)&Wm[(long)(col0 + r) * D + kk + lk];
            Bs[lk + 0][r] = vb.x; Bs[lk + 1][r] = vb.y;
            Bs[lk + 2][r] = vb.z; Bs[lk + 3][r] = vb.w;
        }
        __syncthreads();
        #pragma unroll
        for (int k = 0; k < 16; k++) {
            float4 a0 = *(const float4*)&As[k][ty * 8];
            float4 a1 = *(const float4*)&As[k][ty * 8 + 4];
            float4 b0 = *(const float4*)&Bs[k][tx * 8];
            float4 b1 = *(const float4*)&Bs[k][tx * 8 + 4];
            float a[8] = {a0.x, a0.y, a0.z, a0.w, a1.x, a1.y, a1.z, a1.w};
            float bb[8] = {b0.x, b0.y, b0.z, b0.w, b1.x, b1.y, b1.z, b1.w};
            #pragma unroll
            for (int i = 0; i < 8; i++)
                #pragma unroll
                for (int j = 0; j < 8; j++)
                    acc[i][j] = fmaf(a[i], bb[j], acc[i][j]);
        }
        __syncthreads();
    }
    #pragma unroll
    for (int i = 0; i < 8; i++) {
        int gr = row0 + ty * 8 + i;
        #pragma unroll
        for (int j = 0; j < 8; j += 4) {
            int gc = col0 + tx * 8 + j;
            float4 o;
            o.x = acc[i][j]     + bias[gc];
            o.y = acc[i][j + 1] + bias[gc + 1];
            o.z = acc[i][j + 2] + bias[gc + 2];
            o.w = acc[i][j + 3] + bias[gc + 3];
            *(float4*)&out[(long)gr * D + gc] = o;
        }
    }
}

// ---------------------------------------------------------------------------
// Kernel 4: streaming attention reduce.
// Per block: batch b, 128 q-rows, one m-split of 512 keys (4 tiles of 128).
// scores = q·k^T / 32; online softmax; accumulate num += e*s[m], den += e.
// ---------------------------------------------------------------------------
__global__ __launch_bounds__(256)
void attn_kernel() {
    const int b     = blockIdx.z;
    const int ntile = blockIdx.x;
    const int split = blockIdx.y;
    const int row0  = b * NTOK + ntile * 128;

    __shared__ float Qs[16][132];
    __shared__ float Ks[16][132];
    __shared__ float s_sm[128];

    const int tid = threadIdx.x;
    const int tx = tid & 15, ty = tid >> 4;
    const int lr = tid >> 2;
    const int lk = (tid & 3) << 2;
    const float scale = 0.03125f;  // 1/sqrt(1024)

    float Mrow[8], num[8], den[8];
    #pragma unroll
    for (int i = 0; i < 8; i++) { Mrow[i] = -1e30f; num[i] = 0.f; den[i] = 0.f; }

    for (int mt = 0; mt < 4; mt++) {
        const int mrow0 = b * NTOK + split * 512 + mt * 128;
        __syncthreads();                 // protect s_sm from previous iteration
        if (tid < 128) s_sm[tid] = g_s[mrow0 + tid];
        __syncthreads();

        float acc[8][8];
        #pragma unroll
        for (int i = 0; i < 8; i++)
            #pragma unroll
            for (int j = 0; j < 8; j++) acc[i][j] = 0.f;

        for (int kk = 0; kk < D; kk += 16) {
            #pragma unroll
            for (int s = 0; s < 2; s++) {
                int r = lr + s * 64;
                float4 va = *(const float4*)&g_q[(long)(row0 + r) * D + kk + lk];
                Qs[lk + 0][r] = va.x; Qs[lk + 1][r] = va.y;
                Qs[lk + 2][r] = va.z; Qs[lk + 3][r] = va.w;
                float4 vb = *(const float4*)&g_k[(long)(mrow0 + r) * D + kk + lk];
                Ks[lk + 0][r] = vb.x; Ks[lk + 1][r] = vb.y;
                Ks[lk + 2][r] = vb.z; Ks[lk + 3][r] = vb.w;
            }
            __syncthreads();
            #pragma unroll
            for (int k = 0; k < 16; k++) {
                float4 a0 = *(const float4*)&Qs[k][ty * 8];
                float4 a1 = *(const float4*)&Qs[k][ty * 8 + 4];
                float4 b0 = *(const float4*)&Ks[k][tx * 8];
                float4 b1 = *(const float4*)&Ks[k][tx * 8 + 4];
                float a[8] = {a0.x, a0.y, a0.z, a0.w, a1.x, a1.y, a1.z, a1.w};
                float bb[8] = {b0.x, b0.y, b0.z, b0.w, b1.x, b1.y, b1.z, b1.w};
                #pragma unroll
                for (int i = 0; i < 8; i++)
                    #pragma unroll
                    for (int j = 0; j < 8; j++)
                        acc[i][j] = fmaf(a[i], bb[j], acc[i][j]);
            }
            __syncthreads();
        }

        // online softmax update (16 lanes with same ty own one row group)
        #pragma unroll
        for (int i = 0; i < 8; i++) {
            float tmax = acc[i][0];
            #pragma unroll
            for (int j = 1; j < 8; j++) tmax = fmaxf(tmax, acc[i][j]);
            tmax *= scale;
            #pragma unroll
            for (int off = 1; off < 16; off <<= 1)
                tmax = fmaxf(tmax, __shfl_xor_sync(0xffffffffu, tmax, off));
            float Mnew = fmaxf(Mrow[i], tmax);
            float f = __expf(Mrow[i] - Mnew);
            num[i] *= f; den[i] *= f;
            Mrow[i] = Mnew;
            #pragma unroll
            for (int j = 0; j < 8; j++) {
                float e = __expf(fmaf(acc[i][j], scale, -Mnew));
                den[i] += e;
                num[i] = fmaf(e, s_sm[tx * 8 + j], num[i]);
            }
        }
    }

    // reduce partials across the 16 lanes of each row group
    #pragma unroll
    for (int i = 0; i < 8; i++) {
        #pragma unroll
        for (int off = 1; off < 16; off <<= 1) {
            num[i] += __shfl_xor_sync(0xffffffffu, num[i], off);
            den[i] += __shfl_xor_sync(0xffffffffu, den[i], off);
        }
    }
    if (tx == 0) {
        #pragma unroll
        for (int i = 0; i < 8; i++) {
            int gr = b * NTOK + ntile * 128 + ty * 8 + i;
            float* p = &g_part[(gr * NSPLIT + split) * 3];
            p[0] = Mrow[i]; p[1] = num[i]; p[2] = den[i];
        }
    }
}

// ---------------------------------------------------------------------------
// Kernel 5: combine m-splits (log-sum-exp merge) and add bw
// ---------------------------------------------------------------------------
__global__ void combine_kernel(const float* __restrict__ bw, float* __restrict__ out) {
    int row = blockIdx.x * 256 + threadIdx.x;
    float M = -1e30f;
    #pragma unroll
    for (int s = 0; s < NSPLIT; s++)
        M = fmaxf(M, g_part[(row * NSPLIT + s) * 3]);
    float num = 0.f, den = 0.f;
    #pragma unroll
    for (int s = 0; s < NSPLIT; s++) {
        const float* p = &g_part[(row * NSPLIT + s) * 3];
        float f = __expf(p[0] - M);
        num = fmaf(p[1], f, num);
        den = fmaf(p[2], f, den);
    }
    out[row] = num / den + bw[0];
}

// ---------------------------------------------------------------------------
extern "C" void kernel_launch(void* const* d_in, const int* in_sizes, int n_in,
                              void* d_out, int out_size) {
    const float* x  = (const float*)d_in[0];
    const float* Wq = (const float*)d_in[1];
    const float* bq = (const float*)d_in[2];
    const float* Wk = (const float*)d_in[3];
    const float* bk = (const float*)d_in[4];
    const float* Wv = (const float*)d_in[5];
    const float* bv = (const float*)d_in[6];
    const float* Ww = (const float*)d_in[7];
    const float* bw = (const float*)d_in[8];
    float* out = (float*)d_out;

    prep_u_kernel<<<5, 256>>>(Wv, bv, Ww);
    s_kernel<<<MTOT / 8, 256>>>(x);

    dim3 g3(MTOT / 128, D / 128, 2);
    qk_gemm_kernel<<<g3, 256>>>(x, Wq, bq, Wk, bk);

    dim3 g4(NTOK / 128, NSPLIT, NB);
    attn_kernel<<<g4, 256>>>();

    combine_kernel<<<MTOT / 256, 256>>>(bw, out);
}

// round 2
// speedup vs baseline: 1.0014x; 1.0014x over previous
#include <cuda_runtime.h>

#define D      1024
#define NTOK   2048
#define NB     4
#define MTOT   8192   // NB * NTOK
#define NSPLIT 4

// ---- scratch (device globals: allocation-free rule) ----
__device__ float g_q[MTOT * D];          // 32 MB
__device__ float g_k[MTOT * D];          // 32 MB
__device__ float g_s[MTOT];              // s[b,m] = v[b,m,:]·Ww
__device__ float g_u[D];                 // u = Ww @ Wv
__device__ float g_c;                    // c = Ww · bv
__device__ float g_part[MTOT * NSPLIT * 3]; // per-split (max, num, den)

// ---------------------------------------------------------------------------
// Kernel 1: u[e] = sum_d Ww[d] * Wv[d][e];  c = sum_d Ww[d]*bv[d]
// ---------------------------------------------------------------------------
__global__ void prep_u_kernel(const float* __restrict__ Wv,
                              const float* __restrict__ bv,
                              const float* __restrict__ Ww) {
    if (blockIdx.x < 4) {
        int e = blockIdx.x * 256 + threadIdx.x;
        float sum = 0.f;
        #pragma unroll 8
        for (int d = 0; d < D; d++) sum = fmaf(Ww[d], Wv[d * D + e], sum);
        g_u[e] = sum;
    } else {
        __shared__ float red[256];
        float s = 0.f;
        for (int d = threadIdx.x; d < D; d += 256) s = fmaf(Ww[d], bv[d], s);
        red[threadIdx.x] = s;
        __syncthreads();
        for (int off = 128; off > 0; off >>= 1) {
            if (threadIdx.x < off) red[threadIdx.x] += red[threadIdx.x + off];
            __syncthreads();
        }
        if (threadIdx.x == 0) g_c = red[0];
    }
}

// ---------------------------------------------------------------------------
// Kernel 2: s[row] = x[row,:]·u + c    (one warp per row)
// ---------------------------------------------------------------------------
__global__ void s_kernel(const float* __restrict__ x) {
    int row  = blockIdx.x * 8 + (threadIdx.x >> 5);
    int lane = threadIdx.x & 31;
    const float4* xr = (const float4*)(x + (long)row * D);
    const float4* u4 = (const float4*)g_u;
    float sum = 0.f;
    #pragma unroll
    for (int i = 0; i < 8; i++) {
        float4 a = xr[lane + i * 32];
        float4 b = u4[lane + i * 32];
        sum += a.x * b.x + a.y * b.y + a.z * b.z + a.w * b.w;
    }
    #pragma unroll
    for (int off = 16; off > 0; off >>= 1)
        sum += __shfl_xor_sync(0xffffffffu, sum, off);
    if (lane == 0) g_s[row] = sum + g_c;
}

// ---------------------------------------------------------------------------
// Kernel 3: q = x@Wq^T + bq ; k = x@Wk^T + bk   (blockIdx.z selects q/k)
// 128x128 tile, K-step 16, 256 threads, 8x8 per thread
// ---------------------------------------------------------------------------
__global__ __launch_bounds__(256)
void qk_gemm_kernel(const float* __restrict__ x,
                    const float* __restrict__ Wq, const float* __restrict__ bq,
                    const float* __restrict__ Wk, const float* __restrict__ bk) {
    const float* Wm   = blockIdx.z ? Wk : Wq;
    const float* bias = blockIdx.z ? bk : bq;
    float* out        = blockIdx.z ? g_k : g_q;
    const int row0 = blockIdx.x * 128;
    const int col0 = blockIdx.y * 128;

    __shared__ float As[16][132];
    __shared__ float Bs[16][132];

    const int tid = threadIdx.x;
    const int tx = tid & 15, ty = tid >> 4;
    const int lr = tid >> 2;          // load row (0..63), +64 for second slot
    const int lk = (tid & 3) << 2;    // k offset 0,4,8,12

    float acc[8][8];
    #pragma unroll
    for (int i = 0; i < 8; i++)
        #pragma unroll
        for (int j = 0; j < 8; j++) acc[i][j] = 0.f;

    for (int kk = 0; kk < D; kk += 16) {
        #pragma unroll
        for (int s = 0; s < 2; s++) {
            int r = lr + s * 64;
            float4 va = *(const float4*)&x [(long)(row0 + r) * D + kk + lk];
            As[lk + 0][r] = va.x; As[lk + 1][r] = va.y;
            As[lk + 2][r] = va.z; As[lk + 3][r] = va.w;
            float4 vb = *(const float4*)&Wm[(long)(col0 + r) * D + kk + lk];
            Bs[lk + 0][r] = vb.x; Bs[lk + 1][r] = vb.y;
            Bs[lk + 2][r] = vb.z; Bs[lk + 3][r] = vb.w;
        }
        __syncthreads();
        #pragma unroll
        for (int k = 0; k < 16; k++) {
            float4 a0 = *(const float4*)&As[k][ty * 8];
            float4 a1 = *(const float4*)&As[k][ty * 8 + 4];
            float4 b0 = *(const float4*)&Bs[k][tx * 8];
            float4 b1 = *(const float4*)&Bs[k][tx * 8 + 4];
            float a[8] = {a0.x, a0.y, a0.z, a0.w, a1.x, a1.y, a1.z, a1.w};
            float bb[8] = {b0.x, b0.y, b0.z, b0.w, b1.x, b1.y, b1.z, b1.w};
            #pragma unroll
            for (int i = 0; i < 8; i++)
                #pragma unroll
                for (int j = 0; j < 8; j++)
                    acc[i][j] = fmaf(a[i], bb[j], acc[i][j]);
        }
        __syncthreads();
    }
    #pragma unroll
    for (int i = 0; i < 8; i++) {
        int gr = row0 + ty * 8 + i;
        #pragma unroll
        for (int j = 0; j < 8; j += 4) {
            int gc = col0 + tx * 8 + j;
            float4 o;
            o.x = acc[i][j]     + bias[gc];
            o.y = acc[i][j + 1] + bias[gc + 1];
            o.z = acc[i][j + 2] + bias[gc + 2];
            o.w = acc[i][j + 3] + bias[gc + 3];
            *(float4*)&out[(long)gr * D + gc] = o;
        }
    }
}

// ---------------------------------------------------------------------------
// Kernel 4: streaming attention reduce.
// Per block: batch b, 128 q-rows, one m-split of 512 keys (4 tiles of 128).
// scores = q·k^T / 32; online softmax; accumulate num += e*s[m], den += e.
// ---------------------------------------------------------------------------
__global__ __launch_bounds__(256)
void attn_kernel() {
    const int b     = blockIdx.z;
    const int ntile = blockIdx.x;
    const int split = blockIdx.y;
    const int row0  = b * NTOK + ntile * 128;

    __shared__ float Qs[16][132];
    __shared__ float Ks[16][132];
    __shared__ float s_sm[128];

    const int tid = threadIdx.x;
    const int tx = tid & 15, ty = tid >> 4;
    const int lr = tid >> 2;
    const int lk = (tid & 3) << 2;
    const float scale = 0.03125f;  // 1/sqrt(1024)

    float Mrow[8], num[8], den[8];
    #pragma unroll
    for (int i = 0; i < 8; i++) { Mrow[i] = -1e30f; num[i] = 0.f; den[i] = 0.f; }

    for (int mt = 0; mt < 4; mt++) {
        const int mrow0 = b * NTOK + split * 512 + mt * 128;
        __syncthreads();                 // protect s_sm from previous iteration
        if (tid < 128) s_sm[tid] = g_s[mrow0 + tid];
        __syncthreads();

        float acc[8][8];
        #pragma unroll
        for (int i = 0; i < 8; i++)
            #pragma unroll
            for (int j = 0; j < 8; j++) acc[i][j] = 0.f;

        for (int kk = 0; kk < D; kk += 16) {
            #pragma unroll
            for (int s = 0; s < 2; s++) {
                int r = lr + s * 64;
                float4 va = *(const float4*)&g_q[(long)(row0 + r) * D + kk + lk];
                Qs[lk + 0][r] = va.x; Qs[lk + 1][r] = va.y;
                Qs[lk + 2][r] = va.z; Qs[lk + 3][r] = va.w;
                float4 vb = *(const float4*)&g_k[(long)(mrow0 + r) * D + kk + lk];
                Ks[lk + 0][r] = vb.x; Ks[lk + 1][r] = vb.y;
                Ks[lk + 2][r] = vb.z; Ks[lk + 3][r] = vb.w;
            }
            __syncthreads();
            #pragma unroll
            for (int k = 0; k < 16; k++) {
                float4 a0 = *(const float4*)&Qs[k][ty * 8];
                float4 a1 = *(const float4*)&Qs[k][ty * 8 + 4];
                float4 b0 = *(const float4*)&Ks[k][tx * 8];
                float4 b1 = *(const float4*)&Ks[k][tx * 8 + 4];
                float a[8] = {a0.x, a0.y, a0.z, a0.w, a1.x, a1.y, a1.z, a1.w};
                float bb[8] = {b0.x, b0.y, b0.z, b0.w, b1.x, b1.y, b1.z, b1.w};
                #pragma unroll
                for (int i = 0; i < 8; i++)
                    #pragma unroll
                    for (int j = 0; j < 8; j++)
                        acc[i][j] = fmaf(a[i], bb[j], acc[i][j]);
            }
            __syncthreads();
        }

        // online softmax update (16 lanes with same ty own one row group)
        #pragma unroll
        for (int i = 0; i < 8; i++) {
            float tmax = acc[i][0];
            #pragma unroll
            for (int j = 1; j < 8; j++) tmax = fmaxf(tmax, acc[i][j]);
            tmax *= scale;
            #pragma unroll
            for (int off = 1; off < 16; off <<= 1)
                tmax = fmaxf(tmax, __shfl_xor_sync(0xffffffffu, tmax, off));
            float Mnew = fmaxf(Mrow[i], tmax);
            float f = __expf(Mrow[i] - Mnew);
            num[i] *= f; den[i] *= f;
            Mrow[i] = Mnew;
            #pragma unroll
            for (int j = 0; j < 8; j++) {
                float e = __expf(fmaf(acc[i][j], scale, -Mnew));
                den[i] += e;
                num[i] = fmaf(e, s_sm[tx * 8 + j], num[i]);
            }
        }
    }

    // reduce partials across the 16 lanes of each row group
    #pragma unroll
    for (int i = 0; i < 8; i++) {
        #pragma unroll
        for (int off = 1; off < 16; off <<= 1) {
            num[i] += __shfl_xor_sync(0xffffffffu, num[i], off);
            den[i] += __shfl_xor_sync(0xffffffffu, den[i], off);
        }
    }
    if (tx == 0) {
        #pragma unroll
        for (int i = 0; i < 8; i++) {
            int gr = b * NTOK + ntile * 128 + ty * 8 + i;
            float* p = &g_part[(gr * NSPLIT + split) * 3];
            p[0] = Mrow[i]; p[1] = num[i]; p[2] = den[i];
        }
    }
}

// ---------------------------------------------------------------------------
// Kernel 5: combine m-splits (log-sum-exp merge) and add bw
// ---------------------------------------------------------------------------
__global__ void combine_kernel(const float* __restrict__ bw, float* __restrict__ out) {
    int row = blockIdx.x * 256 + threadIdx.x;
    float M = -1e30f;
    #pragma unroll
    for (int s = 0; s < NSPLIT; s++)
        M = fmaxf(M, g_part[(row * NSPLIT + s) * 3]);
    float num = 0.f, den = 0.f;
    #pragma unroll
    for (int s = 0; s < NSPLIT; s++) {
        const float* p = &g_part[(row * NSPLIT + s) * 3];
        float f = __expf(p[0] - M);
        num = fmaf(p[1], f, num);
        den = fmaf(p[2], f, den);
    }
    out[row] = num / den + bw[0];
}

// ---------------------------------------------------------------------------
extern "C" void kernel_launch(void* const* d_in, const int* in_sizes, int n_in,
                              void* d_out, int out_size) {
    const float* x  = (const float*)d_in[0];
    const float* Wq = (const float*)d_in[1];
    const float* bq = (const float*)d_in[2];
    const float* Wk = (const float*)d_in[3];
    const float* bk = (const float*)d_in[4];
    const float* Wv = (const float*)d_in[5];
    const float* bv = (const float*)d_in[6];
    const float* Ww = (const float*)d_in[7];
    const float* bw = (const float*)d_in[8];
    float* out = (float*)d_out;

    prep_u_kernel<<<5, 256>>>(Wv, bv, Ww);
    s_kernel<<<MTOT / 8, 256>>>(x);

    dim3 g3(MTOT / 128, D / 128, 2);
    qk_gemm_kernel<<<g3, 256>>>(x, Wq, bq, Wk, bk);

    dim3 g4(NTOK / 128, NSPLIT, NB);
    attn_kernel<<<g4, 256>>>();

    combine_kernel<<<MTOT / 256, 256>>>(bw, out);
}

// round 7
// speedup vs baseline: 4.7916x; 4.7851x over previous
#include <cuda_runtime.h>
#include <cuda_fp16.h>
#include <cstdint>

#define D      1024
#define NTOK   2048
#define NB     4
#define MTOT   8192
#define NSPLIT 8

#define BK 64                     // k-chunk in elements (128 B of fp16)
#define NCH (D / BK)              // 16
#define A_BYTES (128 * 128)       // 128 rows x 128 B
#define STAGE_BYTES (2 * A_BYTES) // A + B tile
#define NSTAGE 3
#define DSM (NSTAGE * STAGE_BYTES)  // 96 KB dynamic smem
#define SWZ(x) ((x) ^ (((x) >> 3) & 0x70))

// ---- scratch (device globals: allocation-free rule) ----
__device__ __half g_xb[MTOT * D];
__device__ __half g_wq[D * D];
__device__ __half g_wk[D * D];
__device__ __half g_q[MTOT * D];
__device__ __half g_k[MTOT * D];
__device__ float  g_s[MTOT];
__device__ float  g_u[D];
__device__ float  g_c;
__device__ float2 g_part[MTOT * NSPLIT];

// ============================ PTX helpers ============================
__device__ __forceinline__ uint32_t smem_u32(const void* p) {
    uint32_t a;
    asm("{ .reg .u64 t; cvta.to.shared.u64 t, %1; cvt.u32.u64 %0, t; }"
        : "=r"(a) : "l"(p));
    return a;
}
__device__ __forceinline__ void cp16(uint32_t dst, const void* src) {
    asm volatile("cp.async.cg.shared.global [%0], [%1], 16;" :: "r"(dst), "l"(src));
}
#define CP_COMMIT() asm volatile("cp.async.commit_group;" ::: "memory")
#define CP_WAIT1()  asm volatile("cp.async.wait_group 1;" ::: "memory")

__device__ __forceinline__ void ldsm4(uint32_t* d, uint32_t addr) {
    asm volatile("ldmatrix.sync.aligned.m8n8.x4.shared.b16 {%0,%1,%2,%3}, [%4];"
                 : "=r"(d[0]), "=r"(d[1]), "=r"(d[2]), "=r"(d[3]) : "r"(addr));
}
__device__ __forceinline__ void mma16816(float* c, const uint32_t* a,
                                         uint32_t b0, uint32_t b1) {
    asm volatile(
        "mma.sync.aligned.m16n8k16.row.col.f32.f16.f16.f32 "
        "{%0,%1,%2,%3}, {%4,%5,%6,%7}, {%8,%9}, {%0,%1,%2,%3};"
        : "+f"(c[0]), "+f"(c[1]), "+f"(c[2]), "+f"(c[3])
        : "r"(a[0]), "r"(a[1]), "r"(a[2]), "r"(a[3]), "r"(b0), "r"(b1));
}

// fast 2^t on the FMA pipe
__device__ __forceinline__ float fexp2(float t) {
    t = fmaxf(t, -60.0f);
    float z = t + 12582912.0f;            // 1.5*2^23 rounding trick
    int   ki = __float_as_int(z);
    float n  = z - 12582912.0f;
    float f  = t - n;
    float p = 0.0013333558f;
    p = fmaf(p, f, 0.0096181291f);
    p = fmaf(p, f, 0.0555041087f);
    p = fmaf(p, f, 0.2402265070f);
    p = fmaf(p, f, 0.6931471806f);
    p = fmaf(p, f, 1.0f);
    return __int_as_float(__float_as_int(p) + (ki << 23));
}

// ============================ GEMM microkernel ============================
// C[128x128] += A[128xD] * B[128xD]^T over full K=D. 256 threads, 8 warps
// (2M x 4N, warp tile 64x32). 3-stage cp.async pipeline, SW128 smem, ldmatrix.
__device__ __forceinline__ void load_chunk(uint32_t sbase, int stage,
                                           const __half* gA,
                                           const __half* gB,
                                           int kk, int tid) {
    uint32_t sA = sbase + stage * STAGE_BYTES;
    uint32_t sB = sA + A_BYTES;
    #pragma unroll
    for (int i = 0; i < 4; i++) {
        int cid = i * 256 + tid;
        int row = cid >> 3, c8 = cid & 7;
        cp16(sA + SWZ(row * 128 + c8 * 16), gA + (size_t)row * D + kk + c8 * 8);
    }
    #pragma unroll
    for (int i = 0; i < 4; i++) {
        int cid = i * 256 + tid;
        int row = cid >> 3, c8 = cid & 7;
        cp16(sB + SWZ(row * 128 + c8 * 16), gB + (size_t)row * D + kk + c8 * 8);
    }
}

__device__ __forceinline__ void gemm_tile(uint32_t sbase,
                                          const __half* gA,
                                          const __half* gB,
                                          int tid, float c[4][4][4]) {
    const int lane = tid & 31, warp = tid >> 5;
    const int mw = warp & 1, nw = warp >> 1;
    const int q2 = lane >> 3, r = lane & 7;
    const int kbh = (q2 >> 1) * 16;        // byte offset of k-half within step
    uint32_t aoff[4], boff[2];
    #pragma unroll
    for (int mt = 0; mt < 4; mt++)
        aoff[mt] = (uint32_t)((mw * 64 + mt * 16 + (q2 & 1) * 8 + r) * 128 + kbh);
    #pragma unroll
    for (int nb = 0; nb < 2; nb++)
        boff[nb] = (uint32_t)((nw * 32 + nb * 16 + (q2 & 1) * 8 + r) * 128 + kbh);

    load_chunk(sbase, 0, gA, gB, 0, tid);  CP_COMMIT();
    load_chunk(sbase, 1, gA, gB, BK, tid); CP_COMMIT();

    #pragma unroll 1
    for (int g = 0; g < NCH; g++) {
        CP_WAIT1();
        __syncthreads();
        if (g + 2 < NCH)
            load_chunk(sbase, (g + 2) % NSTAGE, gA, gB, (g + 2) * BK, tid);
        CP_COMMIT();

        uint32_t sA = sbase + (g % NSTAGE) * STAGE_BYTES;
        uint32_t sB = sA + A_BYTES;
        #pragma unroll
        for (int ks = 0; ks < 4; ks++) {
            int kd = ks * 32;
            uint32_t a[4][4], b[2][4];
            #pragma unroll
            for (int mt = 0; mt < 4; mt++) ldsm4(a[mt], sA + SWZ(aoff[mt] + kd));
            #pragma unroll
            for (int nb = 0; nb < 2; nb++) ldsm4(b[nb], sB + SWZ(boff[nb] + kd));
            #pragma unroll
            for (int mt = 0; mt < 4; mt++)
                #pragma unroll
                for (int nt = 0; nt < 4; nt++)
                    mma16816(c[mt][nt], a[mt],
                             b[nt >> 1][nt & 1], b[nt >> 1][(nt & 1) + 2]);
        }
    }
}

// ============================ small kernels ============================
__global__ void conv_kernel(const float* __restrict__ x,
                            const float* __restrict__ Wq,
                            const float* __restrict__ Wk) {
    int bid = blockIdx.x, t = threadIdx.x;
    const float* src; __half* dst; size_t off;
    if (bid < 4096)       { src = x;  dst = g_xb; off = (size_t)bid * 2048; }
    else if (bid < 4608)  { src = Wq; dst = g_wq; off = (size_t)(bid - 4096) * 2048; }
    else                  { src = Wk; dst = g_wk; off = (size_t)(bid - 4608) * 2048; }
    const float4* s4 = (const float4*)(src + off);
    __half2* d2 = (__half2*)(dst + off);
    #pragma unroll
    for (int i = 0; i < 2; i++) {
        float4 v = s4[i * 256 + t];
        d2[(i * 256 + t) * 2 + 0] = __floats2half2_rn(v.x, v.y);
        d2[(i * 256 + t) * 2 + 1] = __floats2half2_rn(v.z, v.w);
    }
}

__global__ void prep_u_kernel(const float* __restrict__ Wv,
                              const float* __restrict__ bv,
                              const float* __restrict__ Ww) {
    if (blockIdx.x < 4) {
        int e = blockIdx.x * 256 + threadIdx.x;
        float sum = 0.f;
        #pragma unroll 8
        for (int d = 0; d < D; d++) sum = fmaf(Ww[d], Wv[d * D + e], sum);
        g_u[e] = sum;
    } else {
        __shared__ float red[256];
        float s = 0.f;
        for (int d = threadIdx.x; d < D; d += 256) s = fmaf(Ww[d], bv[d], s);
        red[threadIdx.x] = s;
        __syncthreads();
        for (int off = 128; off > 0; off >>= 1) {
            if (threadIdx.x < off) red[threadIdx.x] += red[threadIdx.x + off];
            __syncthreads();
        }
        if (threadIdx.x == 0) g_c = red[0];
    }
}

__global__ void s_kernel(const float* __restrict__ x) {
    int row  = blockIdx.x * 8 + (threadIdx.x >> 5);
    int lane = threadIdx.x & 31;
    const float4* xr = (const float4*)(x + (size_t)row * D);
    const float4* u4 = (const float4*)g_u;
    float sum = 0.f;
    #pragma unroll
    for (int i = 0; i < 8; i++) {
        float4 a = xr[lane + i * 32];
        float4 b = u4[lane + i * 32];
        sum += a.x * b.x + a.y * b.y + a.z * b.z + a.w * b.w;
    }
    #pragma unroll
    for (int off = 16; off > 0; off >>= 1)
        sum += __shfl_xor_sync(0xffffffffu, sum, off);
    if (lane == 0) g_s[row] = sum + g_c;
}

// ============================ projection GEMM ============================
__global__ __launch_bounds__(256, 1)
void proj_kernel(const float* __restrict__ bq, const float* __restrict__ bk) {
    extern __shared__ char dsm[];
    __shared__ float s_bias[128];

    const __half* W    = blockIdx.z ? g_wk : g_wq;
    const float* bias  = blockIdx.z ? bk : bq;
    __half* out        = blockIdx.z ? g_k : g_q;
    const int row0 = blockIdx.x * 128;
    const int col0 = blockIdx.y * 128;
    const int tid  = threadIdx.x;
    uint32_t sbase = smem_u32(dsm);

    if (tid < 128) s_bias[tid] = bias[col0 + tid];

    float cacc[4][4][4];
    #pragma unroll
    for (int a = 0; a < 4; a++)
        #pragma unroll
        for (int b = 0; b < 4; b++)
            #pragma unroll
            for (int e = 0; e < 4; e++) cacc[a][b][e] = 0.f;

    gemm_tile(sbase, g_xb + (size_t)row0 * D, W + (size_t)col0 * D, tid, cacc);

    const int lane = tid & 31, warp = tid >> 5;
    const int mw = warp & 1, nw = warp >> 1;
    const int gq = lane >> 2, tg = lane & 3;
    #pragma unroll
    for (int mt = 0; mt < 4; mt++) {
        int row = row0 + mw * 64 + mt * 16 + gq;
        #pragma unroll
        for (int nt = 0; nt < 4; nt++) {
            int colL = nw * 32 + nt * 8 + 2 * tg;
            float b0 = s_bias[colL], b1 = s_bias[colL + 1];
            float* cc = cacc[mt][nt];
            *(__half2*)&out[(size_t)row * D + col0 + colL] =
                __floats2half2_rn(cc[0] + b0, cc[1] + b1);
            *(__half2*)&out[(size_t)(row + 8) * D + col0 + colL] =
                __floats2half2_rn(cc[2] + b0, cc[3] + b1);
        }
    }
}

// ============================ attention kernel ============================
__global__ __launch_bounds__(256, 1)
void attn_kernel() {
    extern __shared__ char dsm[];
    __shared__ float s_sm[128];
    __shared__ float s_red[128][4][2];

    const int b     = blockIdx.z;
    const int split = blockIdx.y;
    const int nt_q  = blockIdx.x;
    const int row0  = b * NTOK + nt_q * 128;
    const int tid   = threadIdx.x;
    const float CLOG = 0.045084220027780106f;   // log2(e)/sqrt(D)
    uint32_t sbase = smem_u32(dsm);

    const int lane = tid & 31, warp = tid >> 5;
    const int mw = warp & 1, nw = warp >> 1;
    const int gq = lane >> 2, tg = lane & 3;

    float num[4][2], den[4][2];
    #pragma unroll
    for (int mt = 0; mt < 4; mt++)
        #pragma unroll
        for (int h = 0; h < 2; h++) { num[mt][h] = 0.f; den[mt][h] = 0.f; }

    #pragma unroll 1
    for (int blk = 0; blk < 2; blk++) {
        const int kb = b * NTOK + split * 256 + blk * 128;
        if (tid < 128) s_sm[tid] = g_s[kb + tid];

        float cacc[4][4][4];
        #pragma unroll
        for (int a = 0; a < 4; a++)
            #pragma unroll
            for (int c = 0; c < 4; c++)
                #pragma unroll
                for (int e = 0; e < 4; e++) cacc[a][c][e] = 0.f;

        gemm_tile(sbase, g_q + (size_t)row0 * D, g_k + (size_t)kb * D, tid, cacc);

        #pragma unroll
        for (int mt = 0; mt < 4; mt++)
            #pragma unroll
            for (int nt = 0; nt < 4; nt++) {
                int colL = nw * 32 + nt * 8 + 2 * tg;
                float s0 = s_sm[colL], s1 = s_sm[colL + 1];
                float* cc = cacc[mt][nt];
                float e0 = fexp2(fmaf(cc[0], CLOG, -4.0f));
                float e1 = fexp2(fmaf(cc[1], CLOG, -4.0f));
                float e2 = fexp2(fmaf(cc[2], CLOG, -4.0f));
                float e3 = fexp2(fmaf(cc[3], CLOG, -4.0f));
                den[mt][0] += e0 + e1;
                den[mt][1] += e2 + e3;
                num[mt][0] = fmaf(e0, s0, fmaf(e1, s1, num[mt][0]));
                num[mt][1] = fmaf(e2, s0, fmaf(e3, s1, num[mt][1]));
            }
        __syncthreads();   // protect s_sm before next block overwrites
    }

    // reduce over the 4 tg lanes sharing a row
    #pragma unroll
    for (int mt = 0; mt < 4; mt++)
        #pragma unroll
        for (int h = 0; h < 2; h++) {
            num[mt][h] += __shfl_xor_sync(0xffffffffu, num[mt][h], 1);
            num[mt][h] += __shfl_xor_sync(0xffffffffu, num[mt][h], 2);
            den[mt][h] += __shfl_xor_sync(0xffffffffu, den[mt][h], 1);
            den[mt][h] += __shfl_xor_sync(0xffffffffu, den[mt][h], 2);
        }
    if (tg == 0) {
        #pragma unroll
        for (int mt = 0; mt < 4; mt++)
            #pragma unroll
            for (int h = 0; h < 2; h++) {
                int rowl = mw * 64 + mt * 16 + h * 8 + gq;
                s_red[rowl][nw][0] = num[mt][h];
                s_red[rowl][nw][1] = den[mt][h];
            }
    }
    __syncthreads();
    if (tid < 128) {
        float n = 0.f, d = 0.f;
        #pragma unroll
        for (int w = 0; w < 4; w++) { n += s_red[tid][w][0]; d += s_red[tid][w][1]; }
        g_part[(size_t)(row0 + tid) * NSPLIT + split] = make_float2(n, d);
    }
}

// ============================ combine ============================
__global__ void combine_kernel(const float* __restrict__ bw,
                               float* __restrict__ out) {
    int row = blockIdx.x * 256 + threadIdx.x;
    float n = 0.f, d = 0.f;
    #pragma unroll
    for (int s = 0; s < NSPLIT; s++) {
        float2 p = g_part[(size_t)row * NSPLIT + s];
        n += p.x; d += p.y;
    }
    out[row] = n / d + bw[0];
}

// ============================ launcher ============================
extern "C" void kernel_launch(void* const* d_in, const int* in_sizes, int n_in,
                              void* d_out, int out_size) {
    const float* x  = (const float*)d_in[0];
    const float* Wq = (const float*)d_in[1];
    const float* bq = (const float*)d_in[2];
    const float* Wk = (const float*)d_in[3];
    const float* bk = (const float*)d_in[4];
    const float* Wv = (const float*)d_in[5];
    const float* bv = (const float*)d_in[6];
    const float* Ww = (const float*)d_in[7];
    const float* bw = (const float*)d_in[8];
    float* out = (float*)d_out;

    cudaFuncSetAttribute(proj_kernel,
        cudaFuncAttributeMaxDynamicSharedMemorySize, DSM);
    cudaFuncSetAttribute(attn_kernel,
        cudaFuncAttributeMaxDynamicSharedMemorySize, DSM);

    conv_kernel<<<5120, 256>>>(x, Wq, Wk);
    prep_u_kernel<<<5, 256>>>(Wv, bv, Ww);
    s_kernel<<<MTOT / 8, 256>>>(x);

    dim3 g3(MTOT / 128, D / 128, 2);
    proj_kernel<<<g3, 256, DSM>>>(bq, bk);

    dim3 g4(NTOK / 128, NSPLIT, NB);
    attn_kernel<<<g4, 256, DSM>>>();

    combine_kernel<<<MTOT / 256, 256>>>(bw, out);
}

// round 8
// speedup vs baseline: 5.1686x; 1.0787x over previous
#include <cuda_runtime.h>
#include <cuda_fp16.h>
#include <cstdint>

#define D      1024
#define NTOK   2048
#define NB     4
#define MTOT   8192
#define NSPLIT 8

#define BK 64                     // k-chunk in elements (128 B of fp16)
#define NCH (D / BK)              // 16
#define A_BYTES (128 * 128)       // 128 rows x 128 B
#define STAGE_BYTES (2 * A_BYTES) // A + B tile
#define NSTAGE 3
#define DSM (NSTAGE * STAGE_BYTES)  // 96 KB dynamic smem
#define SWZ(x) ((x) ^ (((x) >> 3) & 0x70))

// ---- scratch (device globals: allocation-free rule) ----
__device__ __half g_xb[MTOT * D];
__device__ __half g_wq[D * D];
__device__ __half g_wk[D * D];
__device__ __half g_q[MTOT * D];
__device__ __half g_k[MTOT * D];
__device__ float  g_s[MTOT];
__device__ float  g_u[D];
__device__ float  g_c;
__device__ float2 g_part[MTOT * NSPLIT];

// ============================ PTX helpers ============================
__device__ __forceinline__ uint32_t smem_u32(const void* p) {
    uint32_t a;
    asm("{ .reg .u64 t; cvta.to.shared.u64 t, %1; cvt.u32.u64 %0, t; }"
        : "=r"(a) : "l"(p));
    return a;
}
__device__ __forceinline__ void cp16(uint32_t dst, const void* src) {
    asm volatile("cp.async.cg.shared.global [%0], [%1], 16;" :: "r"(dst), "l"(src));
}
#define CP_COMMIT() asm volatile("cp.async.commit_group;" ::: "memory")
#define CP_WAIT1()  asm volatile("cp.async.wait_group 1;" ::: "memory")

__device__ __forceinline__ void ldsm4(uint32_t* d, uint32_t addr) {
    asm volatile("ldmatrix.sync.aligned.m8n8.x4.shared.b16 {%0,%1,%2,%3}, [%4];"
                 : "=r"(d[0]), "=r"(d[1]), "=r"(d[2]), "=r"(d[3]) : "r"(addr));
}
__device__ __forceinline__ void mma16816(float* c, const uint32_t* a,
                                         uint32_t b0, uint32_t b1) {
    asm volatile(
        "mma.sync.aligned.m16n8k16.row.col.f32.f16.f16.f32 "
        "{%0,%1,%2,%3}, {%4,%5,%6,%7}, {%8,%9}, {%0,%1,%2,%3};"
        : "+f"(c[0]), "+f"(c[1]), "+f"(c[2]), "+f"(c[3])
        : "r"(a[0]), "r"(a[1]), "r"(a[2]), "r"(a[3]), "r"(b0), "r"(b1));
}

// fast 2^t on the FMA pipe
__device__ __forceinline__ float fexp2(float t) {
    t = fmaxf(t, -60.0f);
    float z = t + 12582912.0f;            // 1.5*2^23 rounding trick
    int   ki = __float_as_int(z);
    float n  = z - 12582912.0f;
    float f  = t - n;
    float p = 0.0013333558f;
    p = fmaf(p, f, 0.0096181291f);
    p = fmaf(p, f, 0.0555041087f);
    p = fmaf(p, f, 0.2402265070f);
    p = fmaf(p, f, 0.6931471806f);
    p = fmaf(p, f, 1.0f);
    return __int_as_float(__float_as_int(p) + (ki << 23));
}

// ============================ GEMM microkernel ============================
// C[128x128] += A[128xD] * B[128xD]^T over full K=D. 256 threads, 8 warps
// (2M x 4N, warp tile 64x32). 3-stage cp.async pipeline, SW128 smem, ldmatrix.
__device__ __forceinline__ void load_chunk(uint32_t sbase, int stage,
                                           const __half* gA,
                                           const __half* gB,
                                           int kk, int tid) {
    uint32_t sA = sbase + stage * STAGE_BYTES;
    uint32_t sB = sA + A_BYTES;
    #pragma unroll
    for (int i = 0; i < 4; i++) {
        int cid = i * 256 + tid;
        int row = cid >> 3, c8 = cid & 7;
        cp16(sA + SWZ(row * 128 + c8 * 16), gA + (size_t)row * D + kk + c8 * 8);
    }
    #pragma unroll
    for (int i = 0; i < 4; i++) {
        int cid = i * 256 + tid;
        int row = cid >> 3, c8 = cid & 7;
        cp16(sB + SWZ(row * 128 + c8 * 16), gB + (size_t)row * D + kk + c8 * 8);
    }
}

__device__ __forceinline__ void gemm_tile(uint32_t sbase,
                                          const __half* gA,
                                          const __half* gB,
                                          int tid, float c[4][4][4]) {
    const int lane = tid & 31, warp = tid >> 5;
    const int mw = warp & 1, nw = warp >> 1;
    const int q2 = lane >> 3, r = lane & 7;
    const int kbh = (q2 >> 1) * 16;        // byte offset of k-half within step
    uint32_t aoff[4], boff[2];
    #pragma unroll
    for (int mt = 0; mt < 4; mt++)
        aoff[mt] = (uint32_t)((mw * 64 + mt * 16 + (q2 & 1) * 8 + r) * 128 + kbh);
    #pragma unroll
    for (int nb = 0; nb < 2; nb++)
        boff[nb] = (uint32_t)((nw * 32 + nb * 16 + (q2 & 1) * 8 + r) * 128 + kbh);

    load_chunk(sbase, 0, gA, gB, 0, tid);  CP_COMMIT();
    load_chunk(sbase, 1, gA, gB, BK, tid); CP_COMMIT();

    #pragma unroll 1
    for (int g = 0; g < NCH; g++) {
        CP_WAIT1();
        __syncthreads();
        if (g + 2 < NCH)
            load_chunk(sbase, (g + 2) % NSTAGE, gA, gB, (g + 2) * BK, tid);
        CP_COMMIT();

        uint32_t sA = sbase + (g % NSTAGE) * STAGE_BYTES;
        uint32_t sB = sA + A_BYTES;
        #pragma unroll
        for (int ks = 0; ks < 4; ks++) {
            int kd = ks * 32;
            uint32_t a[4][4], b[2][4];
            #pragma unroll
            for (int mt = 0; mt < 4; mt++) ldsm4(a[mt], sA + SWZ(aoff[mt] + kd));
            #pragma unroll
            for (int nb = 0; nb < 2; nb++) ldsm4(b[nb], sB + SWZ(boff[nb] + kd));
            #pragma unroll
            for (int mt = 0; mt < 4; mt++)
                #pragma unroll
                for (int nt = 0; nt < 4; nt++)
                    mma16816(c[mt][nt], a[mt],
                             b[nt >> 1][nt & 1], b[nt >> 1][(nt & 1) + 2]);
        }
    }
}

// ============================ small kernels ============================
__global__ void conv_kernel(const float* __restrict__ x,
                            const float* __restrict__ Wq,
                            const float* __restrict__ Wk) {
    int bid = blockIdx.x, t = threadIdx.x;
    const float* src; __half* dst; size_t off;
    if (bid < 4096)       { src = x;  dst = g_xb; off = (size_t)bid * 2048; }
    else if (bid < 4608)  { src = Wq; dst = g_wq; off = (size_t)(bid - 4096) * 2048; }
    else                  { src = Wk; dst = g_wk; off = (size_t)(bid - 4608) * 2048; }
    const float4* s4 = (const float4*)(src + off);
    __half2* d2 = (__half2*)(dst + off);
    #pragma unroll
    for (int i = 0; i < 2; i++) {
        float4 v = s4[i * 256 + t];
        d2[(i * 256 + t) * 2 + 0] = __floats2half2_rn(v.x, v.y);
        d2[(i * 256 + t) * 2 + 1] = __floats2half2_rn(v.z, v.w);
    }
}

__global__ void prep_u_kernel(const float* __restrict__ Wv,
                              const float* __restrict__ bv,
                              const float* __restrict__ Ww) {
    if (blockIdx.x < 4) {
        int e = blockIdx.x * 256 + threadIdx.x;
        float sum = 0.f;
        #pragma unroll 8
        for (int d = 0; d < D; d++) sum = fmaf(Ww[d], Wv[d * D + e], sum);
        g_u[e] = sum;
    } else {
        __shared__ float red[256];
        float s = 0.f;
        for (int d = threadIdx.x; d < D; d += 256) s = fmaf(Ww[d], bv[d], s);
        red[threadIdx.x] = s;
        __syncthreads();
        for (int off = 128; off > 0; off >>= 1) {
            if (threadIdx.x < off) red[threadIdx.x] += red[threadIdx.x + off];
            __syncthreads();
        }
        if (threadIdx.x == 0) g_c = red[0];
    }
}

__global__ void s_kernel(const float* __restrict__ x) {
    int row  = blockIdx.x * 8 + (threadIdx.x >> 5);
    int lane = threadIdx.x & 31;
    const float4* xr = (const float4*)(x + (size_t)row * D);
    const float4* u4 = (const float4*)g_u;
    float sum = 0.f;
    #pragma unroll
    for (int i = 0; i < 8; i++) {
        float4 a = xr[lane + i * 32];
        float4 b = u4[lane + i * 32];
        sum += a.x * b.x + a.y * b.y + a.z * b.z + a.w * b.w;
    }
    #pragma unroll
    for (int off = 16; off > 0; off >>= 1)
        sum += __shfl_xor_sync(0xffffffffu, sum, off);
    if (lane == 0) g_s[row] = sum + g_c;
}

// ============================ projection GEMM ============================
__global__ __launch_bounds__(256, 2)
void proj_kernel(const float* __restrict__ bq, const float* __restrict__ bk) {
    extern __shared__ char dsm[];
    __shared__ float s_bias[128];

    const __half* W    = blockIdx.z ? g_wk : g_wq;
    const float* bias  = blockIdx.z ? bk : bq;
    __half* out        = blockIdx.z ? g_k : g_q;
    const int row0 = blockIdx.x * 128;
    const int col0 = blockIdx.y * 128;
    const int tid  = threadIdx.x;
    uint32_t sbase = smem_u32(dsm);

    if (tid < 128) s_bias[tid] = bias[col0 + tid];

    float cacc[4][4][4];
    #pragma unroll
    for (int a = 0; a < 4; a++)
        #pragma unroll
        for (int b = 0; b < 4; b++)
            #pragma unroll
            for (int e = 0; e < 4; e++) cacc[a][b][e] = 0.f;

    gemm_tile(sbase, g_xb + (size_t)row0 * D, W + (size_t)col0 * D, tid, cacc);

    const int lane = tid & 31, warp = tid >> 5;
    const int mw = warp & 1, nw = warp >> 1;
    const int gq = lane >> 2, tg = lane & 3;
    #pragma unroll
    for (int mt = 0; mt < 4; mt++) {
        int row = row0 + mw * 64 + mt * 16 + gq;
        #pragma unroll
        for (int nt = 0; nt < 4; nt++) {
            int colL = nw * 32 + nt * 8 + 2 * tg;
            float b0 = s_bias[colL], b1 = s_bias[colL + 1];
            float* cc = cacc[mt][nt];
            *(__half2*)&out[(size_t)row * D + col0 + colL] =
                __floats2half2_rn(cc[0] + b0, cc[1] + b1);
            *(__half2*)&out[(size_t)(row + 8) * D + col0 + colL] =
                __floats2half2_rn(cc[2] + b0, cc[3] + b1);
        }
    }
}

// ============================ attention kernel ============================
__global__ __launch_bounds__(256, 2)
void attn_kernel() {
    extern __shared__ char dsm[];
    __shared__ float s_sm[128];
    __shared__ float s_red[128][4][2];

    const int b     = blockIdx.z;
    const int split = blockIdx.y;
    const int nt_q  = blockIdx.x;
    const int row0  = b * NTOK + nt_q * 128;
    const int tid   = threadIdx.x;
    const float CLOG = 0.045084220027780106f;   // log2(e)/sqrt(D)
    uint32_t sbase = smem_u32(dsm);

    const int lane = tid & 31, warp = tid >> 5;
    const int mw = warp & 1, nw = warp >> 1;
    const int gq = lane >> 2, tg = lane & 3;

    float num[4][2], den[4][2];
    #pragma unroll
    for (int mt = 0; mt < 4; mt++)
        #pragma unroll
        for (int h = 0; h < 2; h++) { num[mt][h] = 0.f; den[mt][h] = 0.f; }

    #pragma unroll 1
    for (int blk = 0; blk < 2; blk++) {
        const int kb = b * NTOK + split * 256 + blk * 128;
        if (tid < 128) s_sm[tid] = g_s[kb + tid];

        float cacc[4][4][4];
        #pragma unroll
        for (int a = 0; a < 4; a++)
            #pragma unroll
            for (int c = 0; c < 4; c++)
                #pragma unroll
                for (int e = 0; e < 4; e++) cacc[a][c][e] = 0.f;

        gemm_tile(sbase, g_q + (size_t)row0 * D, g_k + (size_t)kb * D, tid, cacc);

        #pragma unroll
        for (int mt = 0; mt < 4; mt++)
            #pragma unroll
            for (int nt = 0; nt < 4; nt++) {
                int colL = nw * 32 + nt * 8 + 2 * tg;
                float s0 = s_sm[colL], s1 = s_sm[colL + 1];
                float* cc = cacc[mt][nt];
                float e0 = fexp2(fmaf(cc[0], CLOG, -4.0f));
                float e1 = fexp2(fmaf(cc[1], CLOG, -4.0f));
                float e2 = fexp2(fmaf(cc[2], CLOG, -4.0f));
                float e3 = fexp2(fmaf(cc[3], CLOG, -4.0f));
                den[mt][0] += e0 + e1;
                den[mt][1] += e2 + e3;
                num[mt][0] = fmaf(e0, s0, fmaf(e1, s1, num[mt][0]));
                num[mt][1] = fmaf(e2, s0, fmaf(e3, s1, num[mt][1]));
            }
        __syncthreads();   // protect s_sm before next block overwrites
    }

    // reduce over the 4 tg lanes sharing a row
    #pragma unroll
    for (int mt = 0; mt < 4; mt++)
        #pragma unroll
        for (int h = 0; h < 2; h++) {
            num[mt][h] += __shfl_xor_sync(0xffffffffu, num[mt][h], 1);
            num[mt][h] += __shfl_xor_sync(0xffffffffu, num[mt][h], 2);
            den[mt][h] += __shfl_xor_sync(0xffffffffu, den[mt][h], 1);
            den[mt][h] += __shfl_xor_sync(0xffffffffu, den[mt][h], 2);
        }
    if (tg == 0) {
        #pragma unroll
        for (int mt = 0; mt < 4; mt++)
            #pragma unroll
            for (int h = 0; h < 2; h++) {
                int rowl = mw * 64 + mt * 16 + h * 8 + gq;
                s_red[rowl][nw][0] = num[mt][h];
                s_red[rowl][nw][1] = den[mt][h];
            }
    }
    __syncthreads();
    if (tid < 128) {
        float n = 0.f, d = 0.f;
        #pragma unroll
        for (int w = 0; w < 4; w++) { n += s_red[tid][w][0]; d += s_red[tid][w][1]; }
        g_part[(size_t)(row0 + tid) * NSPLIT + split] = make_float2(n, d);
    }
}

// ============================ combine ============================
__global__ void combine_kernel(const float* __restrict__ bw,
                               float* __restrict__ out) {
    int row = blockIdx.x * 256 + threadIdx.x;
    float n = 0.f, d = 0.f;
    #pragma unroll
    for (int s = 0; s < NSPLIT; s++) {
        float2 p = g_part[(size_t)row * NSPLIT + s];
        n += p.x; d += p.y;
    }
    out[row] = n / d + bw[0];
}

// ============================ launcher ============================
extern "C" void kernel_launch(void* const* d_in, const int* in_sizes, int n_in,
                              void* d_out, int out_size) {
    const float* x  = (const float*)d_in[0];
    const float* Wq = (const float*)d_in[1];
    const float* bq = (const float*)d_in[2];
    const float* Wk = (const float*)d_in[3];
    const float* bk = (const float*)d_in[4];
    const float* Wv = (const float*)d_in[5];
    const float* bv = (const float*)d_in[6];
    const float* Ww = (const float*)d_in[7];
    const float* bw = (const float*)d_in[8];
    float* out = (float*)d_out;

    cudaFuncSetAttribute(proj_kernel,
        cudaFuncAttributeMaxDynamicSharedMemorySize, DSM);
    cudaFuncSetAttribute(attn_kernel,
        cudaFuncAttributeMaxDynamicSharedMemorySize, DSM);

    conv_kernel<<<5120, 256>>>(x, Wq, Wk);
    prep_u_kernel<<<5, 256>>>(Wv, bv, Ww);
    s_kernel<<<MTOT / 8, 256>>>(x);

    dim3 g3(MTOT / 128, D / 128, 2);
    proj_kernel<<<g3, 256, DSM>>>(bq, bk);

    dim3 g4(NTOK / 128, NSPLIT, NB);
    attn_kernel<<<g4, 256, DSM>>>();

    combine_kernel<<<MTOT / 256, 256>>>(bw, out);
}

// round 10
// speedup vs baseline: 5.5270x; 1.0693x over previous
#include <cuda_runtime.h>
#include <cuda_fp16.h>
#include <cstdint>

#define D      1024
#define NTOK   2048
#define NB     4
#define MTOT   8192
#define NSPLIT 8

#define BK 64                       // k-chunk in elements (128 B of fp16)
#define NCH (D / BK)                // 16
#define BLK_BYTES 16384             // one 128x64 fp16 swizzled block
#define A_BYTES   BLK_BYTES
#define STAGE_BYTES (2 * BLK_BYTES) // A + B block
#define NSTAGE 3
#define DSM (NSTAGE * STAGE_BYTES + 1024)   // + align slack
#define SWZ(x) ((x) ^ (((x) >> 3) & 0x70))

// Block layout for a [R x 1024] fp16 matrix (R multiple of 128):
//   byte(row, col) = ((row>>7)*16 + (col>>6))*16384 + SWZ((row&127)*128 + (col&63)*2)
// Each (tile, chunk) block is a contiguous, pre-swizzled 16 KB smem image.

// ---- scratch (device globals: allocation-free rule) ----
__device__ __half g_xb[MTOT * D];
__device__ __half g_wq[D * D];
__device__ __half g_wk[D * D];
__device__ __half g_q[MTOT * D];
__device__ __half g_k[MTOT * D];
__device__ float  g_s[MTOT];
__device__ float  g_u[D];
__device__ float  g_c;
__device__ float2 g_part[MTOT * NSPLIT];

// ============================ PTX helpers ============================
__device__ __forceinline__ uint32_t smem_u32(const void* p) {
    uint32_t a;
    asm("{ .reg .u64 t; cvta.to.shared.u64 t, %1; cvt.u32.u64 %0, t; }"
        : "=r"(a) : "l"(p));
    return a;
}
__device__ __forceinline__ uint32_t h2_bits(__half2 h) {
    union { __half2 h; uint32_t u; } cv;
    cv.h = h;
    return cv.u;
}
__device__ __forceinline__ void mbar_init(uint32_t bar, uint32_t cnt) {
    asm volatile("mbarrier.init.shared.b64 [%0], %1;" :: "r"(bar), "r"(cnt) : "memory");
}
__device__ __forceinline__ void expect_tx(uint32_t bar, uint32_t bytes) {
    asm volatile("mbarrier.arrive.expect_tx.shared.b64 _, [%0], %1;"
                 :: "r"(bar), "r"(bytes) : "memory");
}
__device__ __forceinline__ void bulk_g2s(uint32_t dst, const void* src,
                                         uint32_t bytes, uint32_t bar) {
    asm volatile(
        "cp.async.bulk.shared::cluster.global.mbarrier::complete_tx::bytes "
        "[%0], [%1], %2, [%3];"
        :: "r"(dst), "l"(src), "r"(bytes), "r"(bar) : "memory");
}
__device__ __forceinline__ void bar_wait(uint32_t bar, uint32_t parity) {
    asm volatile(
        "{\n\t.reg .pred P;\n"
        "W%=:\n\t"
        "mbarrier.try_wait.parity.shared.b64 P, [%0], %1;\n\t"
        "@!P bra W%=;\n\t}"
        :: "r"(bar), "r"(parity) : "memory");
}
#define FENCE_ASYNC() asm volatile("fence.proxy.async.shared::cta;" ::: "memory")

__device__ __forceinline__ void ldsm4(uint32_t* d, uint32_t addr) {
    asm volatile("ldmatrix.sync.aligned.m8n8.x4.shared.b16 {%0,%1,%2,%3}, [%4];"
                 : "=r"(d[0]), "=r"(d[1]), "=r"(d[2]), "=r"(d[3]) : "r"(addr));
}
__device__ __forceinline__ void mma16816(float* c, const uint32_t* a,
                                         uint32_t b0, uint32_t b1) {
    asm volatile(
        "mma.sync.aligned.m16n8k16.row.col.f32.f16.f16.f32 "
        "{%0,%1,%2,%3}, {%4,%5,%6,%7}, {%8,%9}, {%0,%1,%2,%3};"
        : "+f"(c[0]), "+f"(c[1]), "+f"(c[2]), "+f"(c[3])
        : "r"(a[0]), "r"(a[1]), "r"(a[2]), "r"(a[3]), "r"(b0), "r"(b1));
}

// fast 2^t on the FMA pipe
__device__ __forceinline__ float fexp2(float t) {
    t = fmaxf(t, -60.0f);
    float z = t + 12582912.0f;            // 1.5*2^23 rounding trick
    int   ki = __float_as_int(z);
    float n  = z - 12582912.0f;
    float f  = t - n;
    float p = 0.0013333558f;
    p = fmaf(p, f, 0.0096181291f);
    p = fmaf(p, f, 0.0555041087f);
    p = fmaf(p, f, 0.2402265070f);
    p = fmaf(p, f, 0.6931471806f);
    p = fmaf(p, f, 1.0f);
    return __int_as_float(__float_as_int(p) + (ki << 23));
}

// ============================ GEMM microkernel ============================
// C[128x128] += A_tile * B_tile^T over K=1024, operands in pre-swizzled block
// layout. 3-stage bulk-copy pipeline; cnt[] carries mbar phases across calls.
__device__ __forceinline__ void gemm_tile(uint32_t sbase, uint32_t mbar,
                                          const char* srcA, const char* srcB,
                                          int tid, int cnt[NSTAGE],
                                          float c[4][4][4]) {
    const int lane = tid & 31, warp = tid >> 5;
    const int mw = warp & 1, nw = warp >> 1;
    const int q2 = lane >> 3, r = lane & 7;
    const int kbh = (q2 >> 1) * 16;
    uint32_t aoff[4], boff[2];
    #pragma unroll
    for (int mt = 0; mt < 4; mt++)
        aoff[mt] = (uint32_t)((mw * 64 + mt * 16 + (q2 & 1) * 8 + r) * 128 + kbh);
    #pragma unroll
    for (int nb = 0; nb < 2; nb++)
        boff[nb] = (uint32_t)((nw * 32 + nb * 16 + (q2 & 1) * 8 + r) * 128 + kbh);

    if (tid == 0) {
        #pragma unroll
        for (int s = 0; s < NSTAGE; s++) {
            expect_tx(mbar + s * 8, 2 * BLK_BYTES);
            bulk_g2s(sbase + s * STAGE_BYTES,           srcA + s * BLK_BYTES,
                     BLK_BYTES, mbar + s * 8);
            bulk_g2s(sbase + s * STAGE_BYTES + A_BYTES, srcB + s * BLK_BYTES,
                     BLK_BYTES, mbar + s * 8);
        }
    }

    #pragma unroll 1
    for (int g = 0; g < NCH; g++) {
        int s = g % NSTAGE;
        bar_wait(mbar + s * 8, cnt[s] & 1);
        cnt[s]++;

        uint32_t sA = sbase + s * STAGE_BYTES;
        uint32_t sB = sA + A_BYTES;
        #pragma unroll
        for (int ks = 0; ks < 4; ks++) {
            int kd = ks * 32;
            uint32_t a[4][4], b[2][4];
            #pragma unroll
            for (int mt = 0; mt < 4; mt++) ldsm4(a[mt], sA + SWZ(aoff[mt] + kd));
            #pragma unroll
            for (int nb = 0; nb < 2; nb++) ldsm4(b[nb], sB + SWZ(boff[nb] + kd));
            #pragma unroll
            for (int mt = 0; mt < 4; mt++)
                #pragma unroll
                for (int nt = 0; nt < 4; nt++)
                    mma16816(c[mt][nt], a[mt],
                             b[nt >> 1][nt & 1], b[nt >> 1][(nt & 1) + 2]);
        }
        __syncthreads();                  // all threads done reading stage s
        if (tid == 0 && g + NSTAGE < NCH) {
            expect_tx(mbar + s * 8, 2 * BLK_BYTES);
            bulk_g2s(sA,           srcA + (g + NSTAGE) * BLK_BYTES,
                     BLK_BYTES, mbar + s * 8);
            bulk_g2s(sA + A_BYTES, srcB + (g + NSTAGE) * BLK_BYTES,
                     BLK_BYTES, mbar + s * 8);
        }
    }
}

// barrier setup shared by both big kernels
__device__ __forceinline__ void mbar_setup(uint32_t mbar, int tid) {
    if (tid == 0) {
        #pragma unroll
        for (int s = 0; s < NSTAGE; s++) mbar_init(mbar + s * 8, 1);
        FENCE_ASYNC();
    }
    __syncthreads();
}

// ============================ small kernels ============================
// fp32 -> fp16 swizzled-block conversion for x, Wq, Wk (8 elems/thread)
__global__ void conv_kernel(const float* __restrict__ x,
                            const float* __restrict__ Wq,
                            const float* __restrict__ Wk) {
    size_t gid = (size_t)blockIdx.x * 256 + threadIdx.x;
    size_t e = gid * 8;
    const float* src; char* dst; size_t off;
    if (e < (size_t)MTOT * D)        { src = x;  dst = (char*)g_xb; off = e; }
    else if (e < (size_t)MTOT*D + (size_t)D*D)
                                     { src = Wq; dst = (char*)g_wq; off = e - (size_t)MTOT*D; }
    else                             { src = Wk; dst = (char*)g_wk; off = e - (size_t)MTOT*D - (size_t)D*D; }
    int row = (int)(off >> 10);
    int col = (int)(off & 1023);
    const float4* s4 = (const float4*)(src + off);
    float4 v0 = s4[0], v1 = s4[1];
    uint4 o;
    o.x = h2_bits(__floats2half2_rn(v0.x, v0.y));
    o.y = h2_bits(__floats2half2_rn(v0.z, v0.w));
    o.z = h2_bits(__floats2half2_rn(v1.x, v1.y));
    o.w = h2_bits(__floats2half2_rn(v1.z, v1.w));
    uint32_t inblk = SWZ((uint32_t)((row & 127) * 128 + (col & 63) * 2));
    size_t byte = ((size_t)((row >> 7) * 16 + (col >> 6))) * BLK_BYTES + inblk;
    *(uint4*)(dst + byte) = o;
}

__global__ void prep_u_kernel(const float* __restrict__ Wv,
                              const float* __restrict__ bv,
                              const float* __restrict__ Ww) {
    if (blockIdx.x < 4) {
        int e = blockIdx.x * 256 + threadIdx.x;
        float sum = 0.f;
        #pragma unroll 8
        for (int d = 0; d < D; d++) sum = fmaf(Ww[d], Wv[d * D + e], sum);
        g_u[e] = sum;
    } else {
        __shared__ float red[256];
        float s = 0.f;
        for (int d = threadIdx.x; d < D; d += 256) s = fmaf(Ww[d], bv[d], s);
        red[threadIdx.x] = s;
        __syncthreads();
        for (int off = 128; off > 0; off >>= 1) {
            if (threadIdx.x < off) red[threadIdx.x] += red[threadIdx.x + off];
            __syncthreads();
        }
        if (threadIdx.x == 0) g_c = red[0];
    }
}

__global__ void s_kernel(const float* __restrict__ x) {
    int row  = blockIdx.x * 8 + (threadIdx.x >> 5);
    int lane = threadIdx.x & 31;
    const float4* xr = (const float4*)(x + (size_t)row * D);
    const float4* u4 = (const float4*)g_u;
    float sum = 0.f;
    #pragma unroll
    for (int i = 0; i < 8; i++) {
        float4 a = xr[lane + i * 32];
        float4 b = u4[lane + i * 32];
        sum += a.x * b.x + a.y * b.y + a.z * b.z + a.w * b.w;
    }
    #pragma unroll
    for (int off = 16; off > 0; off >>= 1)
        sum += __shfl_xor_sync(0xffffffffu, sum, off);
    if (lane == 0) g_s[row] = sum + g_c;
}

// ============================ projection GEMM ============================
__global__ __launch_bounds__(256, 2)
void proj_kernel(const float* __restrict__ bq, const float* __restrict__ bk) {
    extern __shared__ char dsm[];
    __shared__ __align__(8) uint64_t s_bar[NSTAGE];
    __shared__ float s_bias[128];

    const char* Wb   = blockIdx.z ? (const char*)g_wk : (const char*)g_wq;
    const float* bias = blockIdx.z ? bk : bq;
    char* out         = blockIdx.z ? (char*)g_k : (char*)g_q;
    const int rt   = blockIdx.x;          // row tile
    const int ct   = blockIdx.y;          // col tile (n)
    const int tid  = threadIdx.x;
    uint32_t sbase = (smem_u32(dsm) + 1023u) & ~1023u;
    uint32_t mbar  = smem_u32(s_bar);

    if (tid < 128) s_bias[tid] = bias[ct * 128 + tid];
    mbar_setup(mbar, tid);

    float cacc[4][4][4];
    #pragma unroll
    for (int a = 0; a < 4; a++)
        #pragma unroll
        for (int b = 0; b < 4; b++)
            #pragma unroll
            for (int e = 0; e < 4; e++) cacc[a][b][e] = 0.f;

    int cnt[NSTAGE] = {0, 0, 0};
    gemm_tile(sbase, mbar,
              (const char*)g_xb + (size_t)rt * 16 * BLK_BYTES,
              Wb + (size_t)ct * 16 * BLK_BYTES,
              tid, cnt, cacc);

    const int lane = tid & 31, warp = tid >> 5;
    const int mw = warp & 1, nw = warp >> 1;
    const int gq = lane >> 2, tg = lane & 3;
    #pragma unroll
    for (int mt = 0; mt < 4; mt++) {
        int rowL = mw * 64 + mt * 16 + gq;
        #pragma unroll
        for (int nt = 0; nt < 4; nt++) {
            int colL = nw * 32 + nt * 8 + 2 * tg;       // 0..127 within tile
            int col  = ct * 128 + colL;
            float b0 = s_bias[colL], b1 = s_bias[colL + 1];
            float* cc = cacc[mt][nt];
            size_t blk = ((size_t)(rt * 16 + (col >> 6))) * BLK_BYTES;
            uint32_t cb = (uint32_t)((col & 63) * 2);
            *(  __half2*)(out + blk + SWZ((uint32_t)( rowL       * 128) + cb)) =
                __floats2half2_rn(cc[0] + b0, cc[1] + b1);
            *(  __half2*)(out + blk + SWZ((uint32_t)((rowL + 8)  * 128) + cb)) =
                __floats2half2_rn(cc[2] + b0, cc[3] + b1);
        }
    }
}

// ============================ attention kernel ============================
__global__ __launch_bounds__(256, 2)
void attn_kernel() {
    extern __shared__ char dsm[];
    __shared__ __align__(8) uint64_t s_bar[NSTAGE];
    __shared__ float s_sm[128];
    __shared__ float s_red[128][4][2];

    const int b     = blockIdx.z;
    const int split = blockIdx.y;
    const int nt_q  = blockIdx.x;
    const int row0  = b * NTOK + nt_q * 128;
    const int tid   = threadIdx.x;
    const float CLOG = 0.045084220027780106f;   // log2(e)/sqrt(D)
    uint32_t sbase = (smem_u32(dsm) + 1023u) & ~1023u;
    uint32_t mbar  = smem_u32(s_bar);

    const int lane = tid & 31, warp = tid >> 5;
    const int mw = warp & 1, nw = warp >> 1;
    const int gq = lane >> 2, tg = lane & 3;

    mbar_setup(mbar, tid);

    float num[4][2], den[4][2];
    #pragma unroll
    for (int mt = 0; mt < 4; mt++)
        #pragma unroll
        for (int h = 0; h < 2; h++) { num[mt][h] = 0.f; den[mt][h] = 0.f; }

    int cnt[NSTAGE] = {0, 0, 0};

    #pragma unroll 1
    for (int blk = 0; blk < 2; blk++) {
        const int kb = b * NTOK + split * 256 + blk * 128;
        if (tid < 128) s_sm[tid] = g_s[kb + tid];

        float cacc[4][4][4];
        #pragma unroll
        for (int a = 0; a < 4; a++)
            #pragma unroll
            for (int c = 0; c < 4; c++)
                #pragma unroll
                for (int e = 0; e < 4; e++) cacc[a][c][e] = 0.f;

        gemm_tile(sbase, mbar,
                  (const char*)g_q + (size_t)(row0 >> 7) * 16 * BLK_BYTES,
                  (const char*)g_k + (size_t)(kb   >> 7) * 16 * BLK_BYTES,
                  tid, cnt, cacc);

        #pragma unroll
        for (int mt = 0; mt < 4; mt++)
            #pragma unroll
            for (int nt = 0; nt < 4; nt++) {
                int colL = nw * 32 + nt * 8 + 2 * tg;
                float s0 = s_sm[colL], s1 = s_sm[colL + 1];
                float* cc = cacc[mt][nt];
                float e0 = fexp2(fmaf(cc[0], CLOG, -4.0f));
                float e1 = fexp2(fmaf(cc[1], CLOG, -4.0f));
                float e2 = fexp2(fmaf(cc[2], CLOG, -4.0f));
                float e3 = fexp2(fmaf(cc[3], CLOG, -4.0f));
                den[mt][0] += e0 + e1;
                den[mt][1] += e2 + e3;
                num[mt][0] = fmaf(e0, s0, fmaf(e1, s1, num[mt][0]));
                num[mt][1] = fmaf(e2, s0, fmaf(e3, s1, num[mt][1]));
            }
        __syncthreads();   // protect s_sm before next block overwrites
    }

    // reduce over the 4 tg lanes sharing a row
    #pragma unroll
    for (int mt = 0; mt < 4; mt++)
        #pragma unroll
        for (int h = 0; h < 2; h++) {
            num[mt][h] += __shfl_xor_sync(0xffffffffu, num[mt][h], 1);
            num[mt][h] += __shfl_xor_sync(0xffffffffu, num[mt][h], 2);
            den[mt][h] += __shfl_xor_sync(0xffffffffu, den[mt][h], 1);
            den[mt][h] += __shfl_xor_sync(0xffffffffu, den[mt][h], 2);
        }
    if (tg == 0) {
        #pragma unroll
        for (int mt = 0; mt < 4; mt++)
            #pragma unroll
            for (int h = 0; h < 2; h++) {
                int rowl = mw * 64 + mt * 16 + h * 8 + gq;
                s_red[rowl][nw][0] = num[mt][h];
                s_red[rowl][nw][1] = den[mt][h];
            }
    }
    __syncthreads();
    if (tid < 128) {
        float n = 0.f, d = 0.f;
        #pragma unroll
        for (int w = 0; w < 4; w++) { n += s_red[tid][w][0]; d += s_red[tid][w][1]; }
        g_part[(size_t)(row0 + tid) * NSPLIT + split] = make_float2(n, d);
    }
}

// ============================ combine ============================
__global__ void combine_kernel(const float* __restrict__ bw,
                               float* __restrict__ out) {
    int row = blockIdx.x * 256 + threadIdx.x;
    float n = 0.f, d = 0.f;
    #pragma unroll
    for (int s = 0; s < NSPLIT; s++) {
        float2 p = g_part[(size_t)row * NSPLIT + s];
        n += p.x; d += p.y;
    }
    out[row] = n / d + bw[0];
}

// ============================ launcher ============================
extern "C" void kernel_launch(void* const* d_in, const int* in_sizes, int n_in,
                              void* d_out, int out_size) {
    const float* x  = (const float*)d_in[0];
    const float* Wq = (const float*)d_in[1];
    const float* bq = (const float*)d_in[2];
    const float* Wk = (const float*)d_in[3];
    const float* bk = (const float*)d_in[4];
    const float* Wv = (const float*)d_in[5];
    const float* bv = (const float*)d_in[6];
    const float* Ww = (const float*)d_in[7];
    const float* bw = (const float*)d_in[8];
    float* out = (float*)d_out;

    cudaFuncSetAttribute(proj_kernel,
        cudaFuncAttributeMaxDynamicSharedMemorySize, DSM);
    cudaFuncSetAttribute(attn_kernel,
        cudaFuncAttributeMaxDynamicSharedMemorySize, DSM);

    conv_kernel<<<5120, 256>>>(x, Wq, Wk);
    prep_u_kernel<<<5, 256>>>(Wv, bv, Ww);
    s_kernel<<<MTOT / 8, 256>>>(x);

    dim3 g3(MTOT / 128, D / 128, 2);
    proj_kernel<<<g3, 256, DSM>>>(bq, bk);

    dim3 g4(NTOK / 128, NSPLIT, NB);
    attn_kernel<<<g4, 256, DSM>>>();

    combine_kernel<<<MTOT / 256, 256>>>(bw, out);
}